// round 5
// baseline (speedup 1.0000x reference)
#include <cuda_runtime.h>
#include <cstdint>

// TotalDegree: out[b,t] = monomials of degree<=4 over x[b,0..7], 495 terms,
// lexicographic multiset (preorder-DFS) order.
//
// R5: thread-per-row DFS product chain — each term is ONE register FMUL
// (term(prefix,d) = term(prefix)*x[d]); no gather table, no V table.
// Coalescing via 32-term shared-memory strips: stride-33 slots make both the
// per-thread STS (bank = lane+t) and the per-row flush LDS (bank = row+lane)
// conflict-free. Flush stores are coalesced streaming stores (__stcs).

#define NTERMS  495
#define DIM     8
#define NTHREADS 128          // 4 warps -> 512 blocks, spreads over 152 SMs
#define WARPS   (NTHREADS / 32)
#define SLOT    33            // floats per row slot (32 terms + 1 pad)

__global__ void __launch_bounds__(NTHREADS)
totaldegree_kernel(const float* __restrict__ x, float* __restrict__ out, int nrows) {
    __shared__ float buf[WARPS][32][SLOT];       // 4 * 32 * 33 * 4B = 16896 B
    const int warp = threadIdx.x >> 5;
    const int lane = threadIdx.x & 31;
    const int row  = blockIdx.x * NTHREADS + threadIdx.x;
    const int warp_row0 = blockIdx.x * NTHREADS + warp * 32;
    const int rows_valid = min(32, nrows - warp_row0);   // <=0 means idle warp

    // Row's 8 x values -> registers (two float4 loads, warp-contiguous).
    float xx[8];
    if (row < nrows) {
        const float4* xp = (const float4*)(x + (size_t)row * DIM);
        const float4 a = xp[0], b = xp[1];
        xx[0] = a.x; xx[1] = a.y; xx[2] = a.z; xx[3] = a.w;
        xx[4] = b.x; xx[5] = b.y; xx[6] = b.z; xx[7] = b.w;
    } else {
        #pragma unroll
        for (int i = 0; i < DIM; i++) xx[i] = 0.0f;
    }

    float* slot = buf[warp][lane];
    float* wout = out + (size_t)warp_row0 * NTERMS;

    int n = 0;   // term counter; loops fully unroll so n folds to constants

    // Flush strip s (terms [32s, 32s+cnt)): 32 rows, conflict-free LDS,
    // coalesced streaming STG.
    #define FLUSH(s, cnt) do {                                              \
        __syncwarp();                                                       \
        const float* wb = &buf[warp][0][0];                                 \
        _Pragma("unroll 4")                                                 \
        for (int r = 0; r < 32; r++) {                                      \
            const float v = wb[r * SLOT + lane];                            \
            if (r < rows_valid && lane < (cnt))                             \
                __stcs(&wout[(size_t)r * NTERMS + (s) * 32 + lane], v);     \
        }                                                                   \
        __syncwarp();                                                       \
    } while (0)

    #define EMIT(v) do {                                                    \
        slot[n & 31] = (v);                                                 \
        if ((n & 31) == 31) FLUSH(n >> 5, 32);                              \
        n++;                                                                \
    } while (0)

    EMIT(1.0f);                                   // degree 0
    #pragma unroll
    for (int a = 0; a < DIM; a++) {
        const float p1 = xx[a];
        EMIT(p1);                                 // degree 1
        #pragma unroll
        for (int b = a; b < DIM; b++) {
            const float p2 = p1 * xx[b];
            EMIT(p2);                             // degree 2
            #pragma unroll
            for (int c = b; c < DIM; c++) {
                const float p3 = p2 * xx[c];
                EMIT(p3);                         // degree 3
                #pragma unroll
                for (int d = c; d < DIM; d++)
                    EMIT(p3 * xx[d]);             // degree 4
            }
        }
    }
    // n == 495 here; strip 15 holds terms 480..494 (15 terms).
    FLUSH(15, NTERMS - 15 * 32);

    #undef EMIT
    #undef FLUSH
}

extern "C" void kernel_launch(void* const* d_in, const int* in_sizes, int n_in,
                              void* d_out, int out_size) {
    const float* x = (const float*)d_in[0];
    float* out = (float*)d_out;
    const int nrows = in_sizes[0] / DIM;
    const int blocks = (nrows + NTHREADS - 1) / NTHREADS;   // 512
    totaldegree_kernel<<<blocks, NTHREADS>>>(x, out, nrows);
}

// round 6
// speedup vs baseline: 1.4378x; 1.4378x over previous
#include <cuda_runtime.h>
#include <cstdint>

// TotalDegree: out[b,t] = monomials of degree<=4 over x[b,0..7], 495 terms,
// lexicographic multiset (preorder-DFS) order.
//
// R6: R2's high-occupancy warp-per-row structure, plus:
//  - (lo,hi) pair-offset table packed 4-bytes-per-reg into 8 uint registers,
//    loaded once per warp and amortized over RPW=4 rows
//  - __launch_bounds__(256, 6) caps regs so occupancy stays >= 48 warps/SM
// Inner loop: extract offsets (ALU), 2 LDS, FMUL, coalesced STG.

#define NTERMS 495
#define NVALS  45          // pair values (a,b), 0 <= a <= b <= 8; index 8 == 1.0
#define DIM    8
#define NITER  16          // term t = lane + 32*i (512-padded)
#define RPW    4           // rows per warp
#define NTHREADS 256

constexpr int vid(int a, int b) { return a * 9 - a * (a - 1) / 2 + (b - a); }

// Packed table: reg q (of 8) holds iters 2q, 2q+1 as bytes
//   [ lo(2q)*4, hi(2q)*4, lo(2q+1)*4, hi(2q+1)*4 ]   (offsets <= 176, fit bytes)
// Stored [q][lane] for coalesced one-time load.
struct OffT { unsigned v[8][32]; };
struct Dec  { unsigned char v[NVALS]; };

constexpr OffT make_off() {
    unsigned short tv[512] = {};
    int n = 0;
    const int one = vid(8, 8);                                   // id 44 -> 1.0
    tv[n++] = (unsigned short)(one | (one << 8));                // degree 0
    for (int a = 0; a < DIM; a++) {
        tv[n++] = (unsigned short)(vid(a, 8) | (one << 8));      // degree 1
        for (int b = a; b < DIM; b++) {
            tv[n++] = (unsigned short)(vid(a, b) | (one << 8));  // degree 2
            for (int c = b; c < DIM; c++) {
                tv[n++] = (unsigned short)(vid(a, b) | (vid(c, 8) << 8));      // deg 3
                for (int d = c; d < DIM; d++)
                    tv[n++] = (unsigned short)(vid(a, b) | (vid(c, d) << 8));  // deg 4
            }
        }
    }
    for (int t = n; t < 512; t++) tv[t] = (unsigned short)(one | (one << 8));
    OffT o{};
    for (int q = 0; q < 8; q++)
        for (int lane = 0; lane < 32; lane++) {
            const unsigned e0 = tv[lane + 32 * (2 * q)];
            const unsigned e1 = tv[lane + 32 * (2 * q + 1)];
            o.v[q][lane] = ((e0 & 255u) * 4u)
                         | (((e0 >> 8) * 4u) << 8)
                         | (((e1 & 255u) * 4u) << 16)
                         | (((e1 >> 8) * 4u) << 24);
        }
    return o;
}

constexpr Dec make_dec() {
    Dec d{};
    for (int a = 0; a <= 8; a++)
        for (int b = a; b <= 8; b++)
            d.v[vid(a, b)] = (unsigned char)(a | (b << 4));
    return d;
}

__device__ const OffT g_off = make_off();
__device__ const Dec  g_dec = make_dec();

__global__ void __launch_bounds__(NTHREADS, 6)
totaldegree_kernel(const float* __restrict__ x, float* __restrict__ out, int nrows) {
    __shared__ float s_v[NTHREADS / 32][48];
    const int warp = threadIdx.x >> 5;
    const int lane = threadIdx.x & 31;
    float* V = s_v[warp];

    // One-time per-warp: 8 packed table regs (coalesced 32-bit LDGs).
    unsigned pk[8];
    #pragma unroll
    for (int q = 0; q < 8; q++) pk[q] = g_off.v[q][lane];

    const unsigned d0 = g_dec.v[lane];
    const unsigned d1 = g_dec.v[(lane + 32 < NVALS) ? lane + 32 : NVALS - 1];

    const int row0 = (blockIdx.x * (NTHREADS / 32) + warp) * RPW;

    // prefetch first row's x (lanes 0..7; others hold identity 1.0)
    float xv = 1.0f;
    if (row0 < nrows && lane < DIM) xv = x[(size_t)row0 * DIM + lane];

    #pragma unroll 1
    for (int r = 0; r < RPW; r++) {
        const int row = row0 + r;
        if (row >= nrows) break;

        float xnext = 1.0f;
        if (r + 1 < RPW && row + 1 < nrows && lane < DIM)
            xnext = x[(size_t)(row + 1) * DIM + lane];

        // build the 45 pair values via warp shuffles
        const float a0 = __shfl_sync(0xffffffffu, xv, d0 & 15u);
        const float b0 = __shfl_sync(0xffffffffu, xv, d0 >> 4);
        const float a1 = __shfl_sync(0xffffffffu, xv, d1 & 15u);
        const float b1 = __shfl_sync(0xffffffffu, xv, d1 >> 4);
        __syncwarp();                         // prior row's reads done
        V[lane] = a0 * b0;
        if (lane < NVALS - 32) V[lane + 32] = a1 * b1;
        __syncwarp();                         // writes visible

        const char* Vb = (const char*)V;
        float* o = out + (size_t)row * NTERMS + lane;
        #pragma unroll
        for (int i = 0; i < NITER; i++) {
            const unsigned w  = pk[i >> 1];
            const unsigned lo = (i & 1) ? ((w >> 16) & 255u) : (w & 255u);
            const unsigned hi = (i & 1) ? (w >> 24)          : ((w >> 8) & 255u);
            const float va = *(const float*)(Vb + lo);
            const float vb = *(const float*)(Vb + hi);
            if (i < NITER - 1 || lane < NTERMS - 32 * (NITER - 1))   // lane < 15
                o[32 * i] = va * vb;          // coalesced store
        }

        xv = xnext;
    }
}

extern "C" void kernel_launch(void* const* d_in, const int* in_sizes, int n_in,
                              void* d_out, int out_size) {
    const float* x = (const float*)d_in[0];
    float* out = (float*)d_out;
    const int nrows = in_sizes[0] / DIM;
    const int rows_per_block = (NTHREADS / 32) * RPW;               // 32
    const int blocks = (nrows + rows_per_block - 1) / rows_per_block;  // 2048
    totaldegree_kernel<<<blocks, NTHREADS>>>(x, out, nrows);
}

// round 7
// speedup vs baseline: 1.5690x; 1.0913x over previous
#include <cuda_runtime.h>
#include <cstdint>

// TotalDegree: out[b,t] = monomials of degree<=4 over x[b,0..7], 495 terms,
// lexicographic multiset (preorder-DFS) order.
//
// R7 = R2's low-register warp-per-row body (in-loop ushort table LDG, no
// unpack chains) + R4's RPW=8 row loop with next-row x prefetch to hide the
// cold x load. Expect regs ~34, occupancy >= 80%.

#define NTERMS 495
#define NVALS  45          // pair values (a,b), 0 <= a <= b <= 8; index 8 == 1.0
#define DIM    8
#define NITER  16          // term t = lane + 32*i (512-padded)
#define RPW    8           // rows per warp
#define NTHREADS 256

constexpr int vid(int a, int b) { return a * 9 - a * (a - 1) / 2 + (b - a); }

struct T16 { unsigned short v[512]; };
struct Dec { unsigned char v[NVALS]; };

// Term table in reference (preorder-DFS) order: each term's sorted indices
// split into pair(i0,i1) * pair(i2,i3); two pair-ids packed per ushort.
constexpr T16 make_tbl() {
    T16 t{};
    int n = 0;
    const int one = vid(8, 8);                                   // id 44 -> 1.0
    t.v[n++] = (unsigned short)(one | (one << 8));               // degree 0
    for (int a = 0; a < DIM; a++) {
        t.v[n++] = (unsigned short)(vid(a, 8) | (one << 8));     // degree 1
        for (int b = a; b < DIM; b++) {
            t.v[n++] = (unsigned short)(vid(a, b) | (one << 8)); // degree 2
            for (int c = b; c < DIM; c++) {
                t.v[n++] = (unsigned short)(vid(a, b) | (vid(c, 8) << 8));      // deg 3
                for (int d = c; d < DIM; d++)
                    t.v[n++] = (unsigned short)(vid(a, b) | (vid(c, d) << 8));  // deg 4
            }
        }
    }
    for (int k = n; k < 512; k++) t.v[k] = (unsigned short)(one | (one << 8));
    return t;
}

constexpr Dec make_dec() {
    Dec d{};
    for (int a = 0; a <= 8; a++)
        for (int b = a; b <= 8; b++)
            d.v[vid(a, b)] = (unsigned char)(a | (b << 4));
    return d;
}

__device__ const T16 g_tbl = make_tbl();
__device__ const Dec g_dec = make_dec();

__global__ void __launch_bounds__(NTHREADS)
totaldegree_kernel(const float* __restrict__ x, float* __restrict__ out, int nrows) {
    __shared__ float s_v[NTHREADS / 32][48];
    const int warp = threadIdx.x >> 5;
    const int lane = threadIdx.x & 31;
    float* V = s_v[warp];

    const unsigned d0 = g_dec.v[lane];
    const unsigned d1 = g_dec.v[(lane + 32 < NVALS) ? lane + 32 : NVALS - 1];

    const int row0 = (blockIdx.x * (NTHREADS / 32) + warp) * RPW;

    // prefetch first row's x (lanes 0..7; others hold identity 1.0)
    float xv = 1.0f;
    if (row0 < nrows && lane < DIM) xv = x[(size_t)row0 * DIM + lane];

    #pragma unroll 1
    for (int r = 0; r < RPW; r++) {
        const int row = row0 + r;
        if (row >= nrows) break;

        // prefetch next row's x early; independent of everything below
        float xnext = 1.0f;
        if (r + 1 < RPW && row + 1 < nrows && lane < DIM)
            xnext = x[(size_t)(row + 1) * DIM + lane];

        // build the 45 pair values via warp shuffles
        const float a0 = __shfl_sync(0xffffffffu, xv, d0 & 15u);
        const float b0 = __shfl_sync(0xffffffffu, xv, d0 >> 4);
        const float a1 = __shfl_sync(0xffffffffu, xv, d1 & 15u);
        const float b1 = __shfl_sync(0xffffffffu, xv, d1 >> 4);
        __syncwarp();                         // prior row's V reads done
        V[lane] = a0 * b0;
        if (lane < NVALS - 32) V[lane + 32] = a1 * b1;
        __syncwarp();                         // writes visible

        float* o = out + (size_t)row * NTERMS + lane;
        #pragma unroll
        for (int i = 0; i < NITER; i++) {
            const unsigned p = g_tbl.v[lane + 32 * i];   // L1-hot, 64B/warp
            const float va = V[p & 255u];
            const float vb = V[p >> 8];
            if (i < NITER - 1 || lane < NTERMS - 32 * (NITER - 1))   // lane < 15
                o[32 * i] = va * vb;          // coalesced store
        }

        xv = xnext;
    }
}

extern "C" void kernel_launch(void* const* d_in, const int* in_sizes, int n_in,
                              void* d_out, int out_size) {
    const float* x = (const float*)d_in[0];
    float* out = (float*)d_out;
    const int nrows = in_sizes[0] / DIM;
    const int rows_per_block = (NTHREADS / 32) * RPW;                  // 64
    const int blocks = (nrows + rows_per_block - 1) / rows_per_block;  // 1024
    totaldegree_kernel<<<blocks, NTHREADS>>>(x, out, nrows);
}

// round 8
// speedup vs baseline: 1.6655x; 1.0615x over previous
#include <cuda_runtime.h>
#include <cstdint>

// TotalDegree: out[b,t] = monomials of degree<=4 over x[b,0..7], 495 terms,
// lexicographic multiset (preorder-DFS) order.
//
// R8 = R2 (best wall, occ 88%) + floor-directed tweaks:
//  - __stcs streaming stores: evict-first lines overlap the L2->DRAM drain
//    with the kernel instead of the inter-launch gap (steady-state replay
//    must move 130 MB/iter to DRAM).
//  - term table staged in shared per block (990 B) so table reads leave the
//    LDG/L2 path entirely.

#define NTERMS 495
#define NVALS  45          // pair values (a,b), 0 <= a <= b <= 8; index 8 == 1.0
#define DIM    8
#define NITER  16          // term t = lane + 32*i (512-padded)
#define NTHREADS 256

constexpr int vid(int a, int b) { return a * 9 - a * (a - 1) / 2 + (b - a); }

struct T16 { unsigned short v[512]; };
struct Dec { unsigned char v[NVALS]; };

// Term table in reference (preorder-DFS) order: each term's sorted indices
// split into pair(i0,i1)*pair(i2,i3); two pair-ids packed per ushort.
constexpr T16 make_tbl() {
    T16 t{};
    int n = 0;
    const int one = vid(8, 8);                                   // id 44 -> 1.0
    t.v[n++] = (unsigned short)(one | (one << 8));               // degree 0
    for (int a = 0; a < DIM; a++) {
        t.v[n++] = (unsigned short)(vid(a, 8) | (one << 8));     // degree 1
        for (int b = a; b < DIM; b++) {
            t.v[n++] = (unsigned short)(vid(a, b) | (one << 8)); // degree 2
            for (int c = b; c < DIM; c++) {
                t.v[n++] = (unsigned short)(vid(a, b) | (vid(c, 8) << 8));      // deg 3
                for (int d = c; d < DIM; d++)
                    t.v[n++] = (unsigned short)(vid(a, b) | (vid(c, d) << 8));  // deg 4
            }
        }
    }
    for (int k = n; k < 512; k++) t.v[k] = (unsigned short)(one | (one << 8));
    return t;
}

constexpr Dec make_dec() {
    Dec d{};
    for (int a = 0; a <= 8; a++)
        for (int b = a; b <= 8; b++)
            d.v[vid(a, b)] = (unsigned char)(a | (b << 4));
    return d;
}

__device__ const T16 g_tbl = make_tbl();
__device__ const Dec g_dec = make_dec();

__global__ void __launch_bounds__(NTHREADS)
totaldegree_kernel(const float* __restrict__ x, float* __restrict__ out, int nrows) {
    __shared__ float s_v[NTHREADS / 32][48];       // 45 pair values per warp/row
    __shared__ unsigned short s_tbl[512];          // block-shared term table

    const int warp = threadIdx.x >> 5;
    const int lane = threadIdx.x & 31;
    const int row  = (blockIdx.x << 3) + warp;

    // stage term table once per block (512 ushorts = 1 KB, 2 per thread)
    {
        const unsigned* src = (const unsigned*)g_tbl.v;
        ((unsigned*)s_tbl)[threadIdx.x] = src[threadIdx.x];
    }

    // row's x -> lane registers (lanes 0..7; others hold identity 1.0)
    float xv = 1.0f;
    if (row < nrows && lane < DIM) xv = x[(size_t)row * DIM + lane];

    // build the 45 pair values via warp shuffles
    const unsigned d0 = g_dec.v[lane];
    const unsigned d1 = g_dec.v[(lane + 32 < NVALS) ? lane + 32 : NVALS - 1];
    const float a0 = __shfl_sync(0xffffffffu, xv, d0 & 15u);
    const float b0 = __shfl_sync(0xffffffffu, xv, d0 >> 4);
    const float a1 = __shfl_sync(0xffffffffu, xv, d1 & 15u);
    const float b1 = __shfl_sync(0xffffffffu, xv, d1 >> 4);
    float* V = s_v[warp];
    V[lane] = a0 * b0;
    if (lane < NVALS - 32) V[lane + 32] = a1 * b1;
    __syncthreads();                       // table + V visible

    if (row >= nrows) return;              // warp-uniform

    float* o = out + (size_t)row * NTERMS + lane;
    #pragma unroll
    for (int i = 0; i < NITER; i++) {
        const unsigned p = s_tbl[lane + 32 * i];     // conflict-free LDS.U16
        const float va = V[p & 255u];
        const float vb = V[p >> 8];
        if (i < NITER - 1 || lane < NTERMS - 32 * (NITER - 1))   // lane < 15
            __stcs(o + 32 * i, va * vb);   // coalesced, evict-first streaming store
    }
}

extern "C" void kernel_launch(void* const* d_in, const int* in_sizes, int n_in,
                              void* d_out, int out_size) {
    const float* x = (const float*)d_in[0];
    float* out = (float*)d_out;
    const int nrows = in_sizes[0] / DIM;
    const int blocks = (nrows + 7) / 8;    // 8 warps (rows) per block -> 8192
    totaldegree_kernel<<<blocks, NTHREADS>>>(x, out, nrows);
}

// round 9
// speedup vs baseline: 1.7995x; 1.0805x over previous
#include <cuda_runtime.h>
#include <cstdint>

// TotalDegree: out[b,t] = monomials of degree<=4 over x[b,0..7], 495 terms,
// lexicographic multiset (preorder-DFS) order.
//
// R9 = R8 + per-row term ROTATION for 128B-aligned stores.
// Rows are 495 floats (1980 B): row starts are only 4B-aligned, so a naive
// lane-strided warp store straddles two lines -> 2 L1 wavefronts per STG.
// Rotating the term partition by s0 = (17*row) mod 32 makes
// 495*row + s0 = 0 (mod 32): every 32-term strip is a line-aligned store.

#define NTERMS 495
#define NVALS  45          // pair values (a,b), 0 <= a <= b <= 8; index 8 == 1.0
#define DIM    8
#define NITER  16          // 512-padded term space
#define NTHREADS 256

constexpr int vid(int a, int b) { return a * 9 - a * (a - 1) / 2 + (b - a); }

struct T16 { unsigned short v[512]; };
struct Dec { unsigned char v[NVALS]; };

// Term table in reference (preorder-DFS) order: each term's sorted indices
// split into pair(i0,i1)*pair(i2,i3); two pair-ids packed per ushort.
constexpr T16 make_tbl() {
    T16 t{};
    int n = 0;
    const int one = vid(8, 8);                                   // id 44 -> 1.0
    t.v[n++] = (unsigned short)(one | (one << 8));               // degree 0
    for (int a = 0; a < DIM; a++) {
        t.v[n++] = (unsigned short)(vid(a, 8) | (one << 8));     // degree 1
        for (int b = a; b < DIM; b++) {
            t.v[n++] = (unsigned short)(vid(a, b) | (one << 8)); // degree 2
            for (int c = b; c < DIM; c++) {
                t.v[n++] = (unsigned short)(vid(a, b) | (vid(c, 8) << 8));      // deg 3
                for (int d = c; d < DIM; d++)
                    t.v[n++] = (unsigned short)(vid(a, b) | (vid(c, d) << 8));  // deg 4
            }
        }
    }
    for (int k = n; k < 512; k++) t.v[k] = (unsigned short)(one | (one << 8));
    return t;
}

constexpr Dec make_dec() {
    Dec d{};
    for (int a = 0; a <= 8; a++)
        for (int b = a; b <= 8; b++)
            d.v[vid(a, b)] = (unsigned char)(a | (b << 4));
    return d;
}

__device__ const T16 g_tbl = make_tbl();
__device__ const Dec g_dec = make_dec();

__global__ void __launch_bounds__(NTHREADS)
totaldegree_kernel(const float* __restrict__ x, float* __restrict__ out, int nrows) {
    __shared__ float s_v[NTHREADS / 32][48];       // 45 pair values per warp/row
    __shared__ unsigned short s_tbl[512];          // block-shared term table

    const int warp = threadIdx.x >> 5;
    const int lane = threadIdx.x & 31;
    const int row  = (blockIdx.x << 3) + warp;

    // stage term table once per block (512 ushorts, 1 u32 per thread)
    ((unsigned*)s_tbl)[threadIdx.x] = ((const unsigned*)g_tbl.v)[threadIdx.x];

    // row's x -> lane registers (lanes 0..7; others hold identity 1.0)
    float xv = 1.0f;
    if (row < nrows && lane < DIM) xv = x[(size_t)row * DIM + lane];

    // build the 45 pair values via warp shuffles
    const unsigned d0 = g_dec.v[lane];
    const unsigned d1 = g_dec.v[(lane + 32 < NVALS) ? lane + 32 : NVALS - 1];
    const float a0 = __shfl_sync(0xffffffffu, xv, d0 & 15u);
    const float b0 = __shfl_sync(0xffffffffu, xv, d0 >> 4);
    const float a1 = __shfl_sync(0xffffffffu, xv, d1 & 15u);
    const float b1 = __shfl_sync(0xffffffffu, xv, d1 >> 4);
    float* V = s_v[warp];
    V[lane] = a0 * b0;
    if (lane < NVALS - 32) V[lane + 32] = a1 * b1;
    __syncthreads();                       // table + V visible

    if (row >= nrows) return;              // warp-uniform

    // rotation: 495*row + s0 == 0 (mod 32)  (495 = -17 mod 32)
    const unsigned s0 = ((unsigned)row * 17u) & 31u;
    float* orow = out + (size_t)row * NTERMS;

    #pragma unroll
    for (int i = 0; i < NITER; i++) {
        const unsigned tidx = (s0 + 32u * i + lane) & 511u;   // rotated term id
        const unsigned p = s_tbl[tidx];                       // conflict-free LDS.U16
        const float v = V[p & 255u] * V[p >> 8];
        if (tidx < NTERMS)                                    // drop 17 pad slots
            __stcs(orow + tidx, v);        // 128B-line-aligned streaming store
    }
}

extern "C" void kernel_launch(void* const* d_in, const int* in_sizes, int n_in,
                              void* d_out, int out_size) {
    const float* x = (const float*)d_in[0];
    float* out = (float*)d_out;
    const int nrows = in_sizes[0] / DIM;
    const int blocks = (nrows + 7) / 8;    // 8 rows (warps) per block -> 8192
    totaldegree_kernel<<<blocks, NTHREADS>>>(x, out, nrows);
}

// round 10
// speedup vs baseline: 1.9381x; 1.0770x over previous
#include <cuda_runtime.h>
#include <cstdint>

// TotalDegree: out[b,t] = monomials of degree<=4 over x[b,0..7], 495 terms,
// lexicographic multiset (preorder-DFS) order.
//
// R10 = R9 (rotation-aligned streaming stores) + ROW PAIRING:
// rows r and r+32 share the same rotation s0 = 17*r mod 32, hence the same
// table-index sequence. Each warp processes the pair (rowA, rowA+32) so one
// table LDS feeds two rows' gathers: 56 L1 wavefronts/row instead of 77.
// 128-thread blocks keep grid at 8192 (no wave quantization), and the two
// independent row streams double per-warp ILP.

#define NTERMS 495
#define NVALS  45          // pair values (a,b), 0 <= a <= b <= 8; index 8 == 1.0
#define DIM    8
#define NITER  16          // 512-padded term space
#define NTHREADS 128

constexpr int vid(int a, int b) { return a * 9 - a * (a - 1) / 2 + (b - a); }

struct T16 { unsigned short v[512]; };
struct Dec { unsigned char v[NVALS]; };

constexpr T16 make_tbl() {
    T16 t{};
    int n = 0;
    const int one = vid(8, 8);                                   // id 44 -> 1.0
    t.v[n++] = (unsigned short)(one | (one << 8));               // degree 0
    for (int a = 0; a < DIM; a++) {
        t.v[n++] = (unsigned short)(vid(a, 8) | (one << 8));     // degree 1
        for (int b = a; b < DIM; b++) {
            t.v[n++] = (unsigned short)(vid(a, b) | (one << 8)); // degree 2
            for (int c = b; c < DIM; c++) {
                t.v[n++] = (unsigned short)(vid(a, b) | (vid(c, 8) << 8));      // deg 3
                for (int d = c; d < DIM; d++)
                    t.v[n++] = (unsigned short)(vid(a, b) | (vid(c, d) << 8));  // deg 4
            }
        }
    }
    for (int k = n; k < 512; k++) t.v[k] = (unsigned short)(one | (one << 8));
    return t;
}

constexpr Dec make_dec() {
    Dec d{};
    for (int a = 0; a <= 8; a++)
        for (int b = a; b <= 8; b++)
            d.v[vid(a, b)] = (unsigned char)(a | (b << 4));
    return d;
}

__device__ const T16 g_tbl = make_tbl();
__device__ const Dec g_dec = make_dec();

__global__ void __launch_bounds__(NTHREADS)
totaldegree_kernel(const float* __restrict__ x, float* __restrict__ out, int nrows) {
    __shared__ float s_v[NTHREADS / 32][2][48];    // pair-value tables, 2 rows/warp
    __shared__ unsigned short s_tbl[512];

    const int warp = threadIdx.x >> 5;
    const int lane = threadIdx.x & 31;

    // stage term table (512 u16 = 256 u32; 128 threads load 2 each)
    ((unsigned*)s_tbl)[threadIdx.x]       = ((const unsigned*)g_tbl.v)[threadIdx.x];
    ((unsigned*)s_tbl)[threadIdx.x + 128] = ((const unsigned*)g_tbl.v)[threadIdx.x + 128];

    // global warp id -> row pair (rowA, rowA+32) within a 64-row window
    const int W = blockIdx.x * (NTHREADS / 32) + warp;
    const int rowA = ((W >> 5) << 6) + (W & 31);
    const int rowB = rowA + 32;

    float xa = 1.0f, xb = 1.0f;
    if (rowA < nrows && lane < DIM) xa = x[(size_t)rowA * DIM + lane];
    if (rowB < nrows && lane < DIM) xb = x[(size_t)rowB * DIM + lane];

    // build both 45-entry pair-value tables via warp shuffles
    const unsigned d0 = g_dec.v[lane];
    const unsigned d1 = g_dec.v[(lane + 32 < NVALS) ? lane + 32 : NVALS - 1];
    const float aA0 = __shfl_sync(0xffffffffu, xa, d0 & 15u);
    const float bA0 = __shfl_sync(0xffffffffu, xa, d0 >> 4);
    const float aA1 = __shfl_sync(0xffffffffu, xa, d1 & 15u);
    const float bA1 = __shfl_sync(0xffffffffu, xa, d1 >> 4);
    const float aB0 = __shfl_sync(0xffffffffu, xb, d0 & 15u);
    const float bB0 = __shfl_sync(0xffffffffu, xb, d0 >> 4);
    const float aB1 = __shfl_sync(0xffffffffu, xb, d1 & 15u);
    const float bB1 = __shfl_sync(0xffffffffu, xb, d1 >> 4);
    float* VA = s_v[warp][0];
    float* VB = s_v[warp][1];
    VA[lane] = aA0 * bA0;
    VB[lane] = aB0 * bB0;
    if (lane < NVALS - 32) { VA[lane + 32] = aA1 * bA1; VB[lane + 32] = aB1 * bB1; }
    __syncthreads();                       // table + V visible

    if (rowA >= nrows) return;             // warp-uniform
    const bool hasB = (rowB < nrows);

    // shared rotation: 495*rowA + s0 == 0 (mod 32); rowB = rowA+32 -> same s0
    const unsigned s0 = ((unsigned)rowA * 17u) & 31u;
    float* oA = out + (size_t)rowA * NTERMS;
    float* oB = out + (size_t)rowB * NTERMS;

    #pragma unroll
    for (int i = 0; i < NITER; i++) {
        const unsigned tidx = (s0 + 32u * i + lane) & 511u;   // rotated term id
        const unsigned p = s_tbl[tidx];                        // ONE read, two rows
        const unsigned lo = p & 255u, hi = p >> 8;
        const float vA = VA[lo] * VA[hi];
        const float vB = VB[lo] * VB[hi];
        if (tidx < NTERMS) {                                   // drop 17 pad slots
            __stcs(oA + tidx, vA);         // 128B-line-aligned streaming stores
            if (hasB) __stcs(oB + tidx, vB);
        }
    }
}

extern "C" void kernel_launch(void* const* d_in, const int* in_sizes, int n_in,
                              void* d_out, int out_size) {
    const float* x = (const float*)d_in[0];
    float* out = (float*)d_out;
    const int nrows = in_sizes[0] / DIM;
    const int warps_needed = (nrows + 1) / 2;                         // 2 rows/warp
    const int blocks = (warps_needed + (NTHREADS / 32) - 1) / (NTHREADS / 32);  // 8192
    totaldegree_kernel<<<blocks, NTHREADS>>>(x, out, nrows);
}

// round 11
// speedup vs baseline: 1.9762x; 1.0196x over previous
#include <cuda_runtime.h>
#include <cstdint>

// TotalDegree: out[b,t] = monomials of degree<=4 over x[b,0..7], 495 terms,
// lexicographic multiset (preorder-DFS) order.
//
// R11 = R10 + QUAD-row sharing: rotation s0 = 17*row mod 32 is invariant
// under row -> row+32, so rows {r, r+32, r+64, r+96} share one table-index
// sequence. One table LDS feeds four rows (4 tbl-wf/row), four independent
// streams give 4x ILP. Stores stay 128B-line-aligned via the rotation; B/C/D
// row stores are constant offsets off one base pointer (fold into STG imm).

#define NTERMS 495
#define NVALS  45          // pair values (a,b), 0 <= a <= b <= 8; index 8 == 1.0
#define DIM    8
#define NITER  16          // 512-padded term space
#define NTHREADS 128
#define RSTRIDE 32         // row spacing within a quad
#define QUAD    4

constexpr int vid(int a, int b) { return a * 9 - a * (a - 1) / 2 + (b - a); }

struct T16 { unsigned short v[512]; };
struct Dec { unsigned char v[NVALS]; };

constexpr T16 make_tbl() {
    T16 t{};
    int n = 0;
    const int one = vid(8, 8);                                   // id 44 -> 1.0
    t.v[n++] = (unsigned short)(one | (one << 8));               // degree 0
    for (int a = 0; a < DIM; a++) {
        t.v[n++] = (unsigned short)(vid(a, 8) | (one << 8));     // degree 1
        for (int b = a; b < DIM; b++) {
            t.v[n++] = (unsigned short)(vid(a, b) | (one << 8)); // degree 2
            for (int c = b; c < DIM; c++) {
                t.v[n++] = (unsigned short)(vid(a, b) | (vid(c, 8) << 8));      // deg 3
                for (int d = c; d < DIM; d++)
                    t.v[n++] = (unsigned short)(vid(a, b) | (vid(c, d) << 8));  // deg 4
            }
        }
    }
    for (int k = n; k < 512; k++) t.v[k] = (unsigned short)(one | (one << 8));
    return t;
}

constexpr Dec make_dec() {
    Dec d{};
    for (int a = 0; a <= 8; a++)
        for (int b = a; b <= 8; b++)
            d.v[vid(a, b)] = (unsigned char)(a | (b << 4));
    return d;
}

__device__ const T16 g_tbl = make_tbl();
__device__ const Dec g_dec = make_dec();

__global__ void __launch_bounds__(NTHREADS)
totaldegree_kernel(const float* __restrict__ x, float* __restrict__ out, int nrows) {
    __shared__ float s_v[NTHREADS / 32][QUAD][48];   // 4 pair-value tables/warp
    __shared__ unsigned short s_tbl[512];

    const int warp = threadIdx.x >> 5;
    const int lane = threadIdx.x & 31;

    // stage term table (512 u16 = 256 u32; 128 threads x 2)
    ((unsigned*)s_tbl)[threadIdx.x]       = ((const unsigned*)g_tbl.v)[threadIdx.x];
    ((unsigned*)s_tbl)[threadIdx.x + 128] = ((const unsigned*)g_tbl.v)[threadIdx.x + 128];

    // global warp id -> base row of its quad, within a 128-row window
    const int W = blockIdx.x * (NTHREADS / 32) + warp;
    const int rowA = ((W >> 5) << 7) + (W & 31);     // rows rowA + 32*q, q=0..3

    const unsigned d0 = g_dec.v[lane];
    const unsigned d1 = g_dec.v[(lane + 32 < NVALS) ? lane + 32 : NVALS - 1];

    bool has[QUAD];
    #pragma unroll
    for (int q = 0; q < QUAD; q++) {
        const int row = rowA + q * RSTRIDE;
        has[q] = (row < nrows);
        float xv = 1.0f;
        if (has[q] && lane < DIM) xv = x[(size_t)row * DIM + lane];
        const float a0 = __shfl_sync(0xffffffffu, xv, d0 & 15u);
        const float b0 = __shfl_sync(0xffffffffu, xv, d0 >> 4);
        const float a1 = __shfl_sync(0xffffffffu, xv, d1 & 15u);
        const float b1 = __shfl_sync(0xffffffffu, xv, d1 >> 4);
        s_v[warp][q][lane] = a0 * b0;
        if (lane < NVALS - 32) s_v[warp][q][lane + 32] = a1 * b1;
    }
    __syncthreads();                         // table + V tables visible

    if (rowA >= nrows) return;               // warp-uniform

    const float* VA = s_v[warp][0];
    const float* VB = s_v[warp][1];
    const float* VC = s_v[warp][2];
    const float* VD = s_v[warp][3];

    // shared rotation: 495*rowA + s0 == 0 (mod 32); +32k rows keep same s0
    const unsigned s0 = ((unsigned)rowA * 17u) & 31u;
    float* oA = out + (size_t)rowA * NTERMS;         // rows B/C/D at const offsets

    #pragma unroll
    for (int i = 0; i < NITER; i++) {
        const unsigned tidx = (s0 + 32u * i + lane) & 511u;   // rotated term id
        const unsigned p = s_tbl[tidx];                        // ONE read, 4 rows
        const unsigned lo = p & 255u, hi = p >> 8;
        const float vA = VA[lo] * VA[hi];
        const float vB = VB[lo] * VB[hi];
        const float vC = VC[lo] * VC[hi];
        const float vD = VD[lo] * VD[hi];
        if (tidx < NTERMS) {                                   // drop 17 pad slots
            __stcs(oA + tidx, vA);
            if (has[1]) __stcs(oA + 1 * RSTRIDE * NTERMS + tidx, vB);
            if (has[2]) __stcs(oA + 2 * RSTRIDE * NTERMS + tidx, vC);
            if (has[3]) __stcs(oA + 3 * RSTRIDE * NTERMS + tidx, vD);
        }
    }
}

extern "C" void kernel_launch(void* const* d_in, const int* in_sizes, int n_in,
                              void* d_out, int out_size) {
    const float* x = (const float*)d_in[0];
    float* out = (float*)d_out;
    const int nrows = in_sizes[0] / DIM;
    const int warps_needed = (nrows + QUAD - 1) / QUAD;               // 4 rows/warp
    const int blocks = (warps_needed + (NTHREADS / 32) - 1) / (NTHREADS / 32); // 4096
    totaldegree_kernel<<<blocks, NTHREADS>>>(x, out, nrows);
}